// round 3
// baseline (speedup 1.0000x reference)
#include <cuda_runtime.h>
#include <cstdint>
#include <cstddef>

#define BATCH   16
#define LSEQ    4096
#define INDIM   64
#define DMODEL  128
#define OUTDIM  64
#define TCHUNK  128
#define NCHUNK  32          // LSEQ / TCHUNK
#define CHAINS  256         // 128 p * {re,im}

// ---------------- device scratch (no allocations allowed) ----------------
__device__ float  g_w[(size_t)BATCH * LSEQ * CHAINS];        // local-scan w (67MB)
__device__ float2 g_carry[BATCH * NCHUNK * CHAINS];          // chunk-local final states
__device__ float2 g_cin[BATCH * NCHUNK * CHAINS];            // exclusive cross-chunk prefix
__device__ float  g_BW[CHAINS * INDIM];                      // fused B_part * W_in
__device__ float  g_BuC[CHAINS];                             // B_part * b_in
__device__ float4 g_Pm[TCHUNK * DMODEL];                     // M^{j+1} per p: {m11,m12,m21,m22}
__device__ float  g_WcT[320 * OUTDIM];                       // fused output matrix, [k][o]
__device__ float  g_bias[OUTDIM];

// ---------------- f32x2 / smem helpers ----------------
__device__ __forceinline__ unsigned long long pack2(float lo, float hi) {
    unsigned long long r;
    asm("mov.b64 %0, {%1, %2};" : "=l"(r) : "f"(lo), "f"(hi));
    return r;
}
__device__ __forceinline__ float2 unpack2(unsigned long long v) {
    float lo, hi;
    asm("mov.b64 {%0, %1}, %2;" : "=f"(lo), "=f"(hi) : "l"(v));
    return make_float2(lo, hi);
}
__device__ __forceinline__ unsigned long long fma2(unsigned long long a, unsigned long long b, unsigned long long c) {
    unsigned long long d;
    asm("fma.rn.f32x2 %0, %1, %2, %3;" : "=l"(d) : "l"(a), "l"(b), "l"(c));
    return d;
}
__device__ __forceinline__ unsigned long long add2(unsigned long long a, unsigned long long b) {
    unsigned long long d;
    asm("add.rn.f32x2 %0, %1, %2;" : "=l"(d) : "l"(a), "l"(b));
    return d;
}
__device__ __forceinline__ void lds_v2u64(unsigned long long &a, unsigned long long &b, uint32_t addr) {
    asm volatile("ld.shared.v2.u64 {%0, %1}, [%2];" : "=l"(a), "=l"(b) : "r"(addr));
}
__device__ __forceinline__ uint32_t smem_u32(const void* p) {
    uint32_t a;
    asm("{ .reg .u64 t; cvta.to.shared.u64 t, %1; cvt.u32.u64 %0, t; }" : "=r"(a) : "l"(p));
    return a;
}

// implicit-LinOSS per-p recurrence coefficients
__device__ __forceinline__ void lin_coefs(const float* __restrict__ A_diag,
                                          const float* __restrict__ steps, int p,
                                          float& m11, float& m12, float& m21, float& m22,
                                          float& f1, float& f2) {
    float A  = fmaxf(A_diag[p], 0.0f);
    float dt = 1.0f / (1.0f + expf(-steps[p]));
    float dt2A = dt * dt * A;
    float S  = 1.0f / (1.0f + dt2A);
    m11 = 1.0f - dt2A * S;
    m12 = -dt * A * S;
    m21 = dt * S;
    m22 = S;
    f1  = m11 * dt;
    f2  = m21 * dt;
}

// ================= kernel A: build fused matrices + power table =================
__global__ __launch_bounds__(256) void kA(const float* __restrict__ W_in,
                                          const float* __restrict__ b_in,
                                          const float* __restrict__ A_diag,
                                          const float* __restrict__ Bmat,
                                          const float* __restrict__ Cmat,
                                          const float* __restrict__ Dvec,
                                          const float* __restrict__ steps,
                                          const float* __restrict__ W_out,
                                          const float* __restrict__ b_out) {
    __shared__ float sbuf[11264];
    const int bid = blockIdx.x, tid = threadIdx.x;

    if (bid < 16) {
        // BW[k][i] = sum_h B_part[k][h] * W_in[h][i]; 16 k-rows per block
        float* Wins = sbuf;                   // [128][64]
        float* Bs   = sbuf + DMODEL * INDIM;  // [16][128]
        for (int i = tid; i < DMODEL * INDIM; i += 256) Wins[i] = W_in[i];
        const int k0 = bid * 16;
        for (int i = tid; i < 16 * DMODEL; i += 256) {
            int kk = i >> 7, h = i & 127;
            int k = k0 + kk, p = k & 127, part = k >> 7;
            Bs[i] = Bmat[(p * DMODEL + h) * 2 + part];
        }
        __syncthreads();
        for (int e = tid; e < 16 * INDIM; e += 256) {
            int kk = e >> 6, i = e & 63;
            float acc = 0.0f;
            #pragma unroll 8
            for (int h = 0; h < DMODEL; h++) acc = fmaf(Bs[kk * DMODEL + h], Wins[h * INDIM + i], acc);
            g_BW[(k0 + kk) * INDIM + i] = acc;
        }
        if (bid == 0) {
            int k = tid, p = k & 127, part = k >> 7;
            float s = 0.0f;
            for (int h = 0; h < DMODEL; h++) s = fmaf(Bmat[(p * DMODEL + h) * 2 + part], b_in[h], s);
            g_BuC[k] = s;
        }
    } else if (bid < 32) {
        // WcT rows: k<128: W_out*C_re ; k<256: -W_out*C_im ; else W_out*diag(D)*W_in
        float* Wos = sbuf;                    // [64][129] padded
        float* Cs  = sbuf + OUTDIM * 129;     // [20][128]
        for (int i = tid; i < OUTDIM * DMODEL; i += 256) {
            int o = i >> 7, h = i & 127;
            Wos[o * 129 + h] = W_out[i];
        }
        const int kb0 = (bid - 16) * 20;
        for (int i = tid; i < 20 * DMODEL; i += 256) {
            int kk = i >> 7, h = i & 127;
            int k = kb0 + kk;
            float v;
            if (k < 128)      v =  Cmat[(h * DMODEL + k) * 2 + 0];
            else if (k < 256) v = -Cmat[(h * DMODEL + (k - 128)) * 2 + 1];
            else              v =  Dvec[h] * W_in[h * INDIM + (k - 256)];
            Cs[i] = v;
        }
        __syncthreads();
        for (int e = tid; e < 20 * OUTDIM; e += 256) {
            int kk = e >> 6, o = e & 63;
            float acc = 0.0f;
            #pragma unroll 8
            for (int h = 0; h < DMODEL; h++) acc = fmaf(Cs[kk * DMODEL + h], Wos[o * 129 + h], acc);
            g_WcT[(kb0 + kk) * OUTDIM + o] = acc;
        }
        if (bid == 16 && tid < OUTDIM) {
            float s = b_out[tid];
            for (int h = 0; h < DMODEL; h++) s = fmaf(W_out[tid * DMODEL + h] * Dvec[h], b_in[h], s);
            g_bias[tid] = s;
        }
    } else {
        // power table Pm[j][p] = M^{j+1}
        if (tid < DMODEL) {
            float m11, m12, m21, m22, f1, f2;
            lin_coefs(A_diag, steps, tid, m11, m12, m21, m22, f1, f2);
            float c11 = m11, c12 = m12, c21 = m21, c22 = m22;
            for (int j = 0; j < TCHUNK; j++) {
                g_Pm[j * DMODEL + tid] = make_float4(c11, c12, c21, c22);
                float n11 = m11 * c11 + m12 * c21;
                float n12 = m11 * c12 + m12 * c22;
                float n21 = m21 * c11 + m22 * c21;
                float n22 = m21 * c12 + m22 * c22;
                c11 = n11; c12 = n12; c21 = n21; c22 = n22;
            }
        }
    }
}

// ================= kernel B: fused Bu-GEMM + chunk-local scan =================
__global__ __launch_bounds__(256) void kB(const float* __restrict__ x,
                                          const float* __restrict__ A_diag,
                                          const float* __restrict__ steps) {
    __shared__ float4 xs4[TCHUNK * INDIM / 4];   // 32KB x tile
    const int b = blockIdx.x >> 5, c = blockIdx.x & 31;
    const int tid = threadIdx.x;

    const float4* xg = (const float4*)(x + (size_t)(b * LSEQ + c * TCHUNK) * INDIM);
    #pragma unroll
    for (int i = 0; i < 8; i++) xs4[tid + i * 256] = xg[tid + i * 256];

    const int k = tid, p = k & 127;
    float m11, m12, m21, m22, f1, f2;
    lin_coefs(A_diag, steps, p, m11, m12, m21, m22, f1, f2);

    // BW row in registers, pre-packed for f32x2
    unsigned long long bw2[32];
    {
        const float4* br = (const float4*)(g_BW + k * INDIM);
        #pragma unroll
        for (int i = 0; i < 16; i++) {
            float4 v = br[i];
            bw2[2 * i]     = pack2(v.x, v.y);
            bw2[2 * i + 1] = pack2(v.z, v.w);
        }
    }
    const float buc = g_BuC[k];
    __syncthreads();

    const uint32_t xsb = smem_u32(xs4);
    float z = 0.0f, w = 0.0f;
    float* wout = g_w + (size_t)(b * LSEQ + c * TCHUNK) * CHAINS + k;

    #pragma unroll 2
    for (int t = 0; t < TCHUNK; t++) {
        unsigned long long a0 = 0ull, a1 = 0ull, a2 = 0ull, a3 = 0ull;
        const uint32_t base = xsb + t * 256;
        #pragma unroll
        for (int i = 0; i < 8; i++) {
            unsigned long long xA, xB, xC, xD;
            lds_v2u64(xA, xB, base + i * 32);
            lds_v2u64(xC, xD, base + i * 32 + 16);
            a0 = fma2(bw2[4 * i],     xA, a0);
            a1 = fma2(bw2[4 * i + 1], xB, a1);
            a2 = fma2(bw2[4 * i + 2], xC, a2);
            a3 = fma2(bw2[4 * i + 3], xD, a3);
        }
        float2 sf = unpack2(add2(add2(a0, a1), add2(a2, a3)));
        float bu = sf.x + sf.y + buc;
        float nz = fmaf(m11, z, fmaf(m12, w, f1 * bu));
        float nw = fmaf(m21, z, fmaf(m22, w, f2 * bu));
        z = nz; w = nw;
        wout[(size_t)t * CHAINS] = w;
    }
    g_carry[(b * NCHUNK + c) * CHAINS + k] = make_float2(z, w);
}

// ================= kernel C: cross-chunk scan of carries =================
__global__ __launch_bounds__(256) void kC() {
    const int b = blockIdx.x, k = threadIdx.x, p = k & 127;
    const float4 mt = g_Pm[(TCHUNK - 1) * DMODEL + p];   // M^TCHUNK
    float z = 0.0f, w = 0.0f;
    for (int c = 0; c < NCHUNK; c++) {
        const int idx = (b * NCHUNK + c) * CHAINS + k;
        g_cin[idx] = make_float2(z, w);
        float2 lc = g_carry[idx];
        float nz = fmaf(mt.x, z, fmaf(mt.y, w, lc.x));
        float nw = fmaf(mt.z, z, fmaf(mt.w, w, lc.y));
        z = nz; w = nw;
    }
}

// ================= kernel D: carry fixup + fused output GEMM =================
// out[t][o] = sum_k [w_re | w_im | x][t][k] * WcT[k][o] + bias[o],  K=320
__global__ __launch_bounds__(256) void kD(const float* __restrict__ x,
                                          float* __restrict__ out) {
    __shared__ float As[TCHUNK][33];
    __shared__ float Bs[32 * 64];
    __shared__ float czs[CHAINS], cws[CHAINS];
    __shared__ float biass[OUTDIM];
    const int b = blockIdx.x >> 5, c = blockIdx.x & 31, t0 = c * TCHUNK;
    const int tid = threadIdx.x;

    {
        float2 ci = g_cin[(b * NCHUNK + c) * CHAINS + tid];
        czs[tid] = ci.x; cws[tid] = ci.y;
        if (tid < OUTDIM) biass[tid] = g_bias[tid];
    }

    const int tx = tid & 15, ty = tid >> 4;        // compute: 16 col-groups x 16 row-groups
    const int scol = tid & 31, rbase = (tid >> 5) * 16;  // staging: 32 cols x 8 row-segments
    float acc[8][4];
    #pragma unroll
    for (int r = 0; r < 8; r++) {
        acc[r][0] = 0.f; acc[r][1] = 0.f; acc[r][2] = 0.f; acc[r][3] = 0.f;
    }

    for (int ks = 0; ks < 10; ks++) {
        __syncthreads();
        #pragma unroll
        for (int it = 0; it < 2; it++) {
            int idx = tid + it * 256;
            ((float4*)Bs)[idx] = ((const float4*)(g_WcT + ks * 32 * OUTDIM))[idx];
        }
        if (ks < 8) {
            const int k = ks * 32 + scol;
            const int p = k & 127;
            const float cz = czs[k], cw = cws[k];
            const float* wsrc = g_w + ((size_t)(b * LSEQ) + t0) * CHAINS + k;
            #pragma unroll 4
            for (int j = 0; j < 16; j++) {
                int r = rbase + j;
                float4 pm = g_Pm[r * DMODEL + p];
                As[r][scol] = fmaf(pm.z, cz, fmaf(pm.w, cw, wsrc[(size_t)r * CHAINS]));
            }
        } else {
            const int xi = (ks - 8) * 32 + scol;
            const float* xsrc = x + ((size_t)(b * LSEQ) + t0) * INDIM + xi;
            #pragma unroll 4
            for (int j = 0; j < 16; j++) {
                int r = rbase + j;
                As[r][scol] = xsrc[(size_t)r * INDIM];
            }
        }
        __syncthreads();
        #pragma unroll
        for (int kk = 0; kk < 32; kk++) {
            float4 bv = *(const float4*)(Bs + kk * 64 + tx * 4);
            #pragma unroll
            for (int r = 0; r < 8; r++) {
                float a = As[ty * 8 + r][kk];
                acc[r][0] = fmaf(a, bv.x, acc[r][0]);
                acc[r][1] = fmaf(a, bv.y, acc[r][1]);
                acc[r][2] = fmaf(a, bv.z, acc[r][2]);
                acc[r][3] = fmaf(a, bv.w, acc[r][3]);
            }
        }
    }
    float* og = out + ((size_t)(b * LSEQ) + t0) * OUTDIM;
    float b0 = biass[tx * 4], b1 = biass[tx * 4 + 1], b2 = biass[tx * 4 + 2], b3 = biass[tx * 4 + 3];
    #pragma unroll
    for (int r = 0; r < 8; r++) {
        int row = ty * 8 + r;
        float4 v = make_float4(acc[r][0] + b0, acc[r][1] + b1, acc[r][2] + b2, acc[r][3] + b3);
        *(float4*)(og + (size_t)row * OUTDIM + tx * 4) = v;
    }
}

extern "C" void kernel_launch(void* const* d_in, const int* in_sizes, int n_in,
                              void* d_out, int out_size) {
    const float* x      = (const float*)d_in[0];
    const float* W_in   = (const float*)d_in[1];
    const float* b_in   = (const float*)d_in[2];
    const float* A_diag = (const float*)d_in[3];
    const float* Bmat   = (const float*)d_in[4];
    const float* Cmat   = (const float*)d_in[5];
    const float* Dvec   = (const float*)d_in[6];
    const float* steps  = (const float*)d_in[7];
    const float* W_out  = (const float*)d_in[8];
    const float* b_out  = (const float*)d_in[9];
    float* out = (float*)d_out;

    kA<<<33, 256>>>(W_in, b_in, A_diag, Bmat, Cmat, Dvec, steps, W_out, b_out);
    kB<<<BATCH * NCHUNK, 256>>>(x, A_diag, steps);
    kC<<<BATCH, 256>>>();
    kD<<<BATCH * NCHUNK, 256>>>(x, out);
}